// round 2
// baseline (speedup 1.0000x reference)
#include <cuda_runtime.h>
#include <cuda.h>
#include <cstdint>

// ============================================================================
// TernaryLinear: out[m,n] = sum_k x[m,k] * sign(w[n,k])
//   M = 8192, N = 16384, K = 4096, fp32 in/out.
//
// Exact-integer split GEMM on mma.sync int8 tensor cores (base sm_103 PTX —
// tcgen05 is rejected because the harness emits plain compute_103 PTX):
//   q = round(x * 4096) in [-32640, 32639];  q = hi*256 + lo  (int8, exact)
//   S = sign(w) int8 (exact)
//   y = (256*(hi@S^T) + (lo@S^T)) / 4096     (s32 accumulation, exact)
// Only error: quantization of x -> rel err ~7e-5.
// ============================================================================

#define M_TOTAL 8192
#define K_TOTAL 4096
#define N_TOTAL 16384

// ------------------------- device scratch (no mallocs) ---------------------
__device__ __align__(1024) int8_t g_A_hi[(size_t)M_TOTAL * K_TOTAL];   // 32 MB
__device__ __align__(1024) int8_t g_A_lo[(size_t)M_TOTAL * K_TOTAL];   // 32 MB
__device__ __align__(1024) int8_t g_S[(size_t)N_TOTAL * K_TOTAL];      // 64 MB

// ------------------------------ PTX helpers --------------------------------
__device__ __forceinline__ uint32_t smem_u32(const void* p) {
    uint32_t a;
    asm("{ .reg .u64 t; cvta.to.shared.u64 t, %1; cvt.u32.u64 %0, t; }"
        : "=r"(a) : "l"(p));
    return a;
}

#define MBAR_INIT(addr, cnt) \
    asm volatile("mbarrier.init.shared.b64 [%0], %1;" :: "r"(addr), "r"(cnt) : "memory")

#define MBAR_EXPECT_TX(addr, bytes) \
    asm volatile("mbarrier.arrive.expect_tx.shared.b64 _, [%0], %1;" \
                 :: "r"(addr), "r"(bytes) : "memory")

#define MBAR_WAIT(addr, ph) do {                                              \
    asm volatile("{\n\t.reg .pred P1;\n\t"                                    \
        "WAIT_%=:\n\t"                                                        \
        "mbarrier.try_wait.parity.acquire.cta.shared::cta.b64 P1, [%0], %1, 0x989680;\n\t" \
        "@P1 bra.uni DONE_%=;\n\t"                                            \
        "bra.uni WAIT_%=;\n\t"                                                \
        "DONE_%=:\n\t}"                                                       \
        :: "r"(addr), "r"(ph) : "memory");                                    \
} while (0)

#define TMA_LOAD_2D(dst, map, cx, cy, mbar) \
    asm volatile("cp.async.bulk.tensor.2d.shared::cta.global.tile.mbarrier::complete_tx::bytes " \
                 "[%0], [%1, {%2, %3}], [%4];" \
                 :: "r"(dst), "l"(map), "r"(cx), "r"(cy), "r"(mbar) : "memory")

#define FENCE_PROXY_ASYNC() \
    asm volatile("fence.proxy.async.shared::cta;" ::: "memory")

// ldmatrix 4x (8x8 b16) — byte layout coincides with s8 mma fragments
#define LDSM4(r0, r1, r2, r3, addr)                                           \
    asm volatile("ldmatrix.sync.aligned.m8n8.x4.shared.b16 {%0,%1,%2,%3}, [%4];" \
        : "=r"(r0), "=r"(r1), "=r"(r2), "=r"(r3) : "r"(addr))

#define MMA_S8(d, a, b0, b1)                                                  \
    asm volatile("mma.sync.aligned.m16n8k32.row.col.s32.s8.s8.s32 "           \
        "{%0,%1,%2,%3}, {%4,%5,%6,%7}, {%8,%9}, {%0,%1,%2,%3};"               \
        : "+r"((d)[0]), "+r"((d)[1]), "+r"((d)[2]), "+r"((d)[3])              \
        : "r"((a)[0]), "r"((a)[1]), "r"((a)[2]), "r"((a)[3]),                 \
          "r"(b0), "r"(b1))

// ------------------------------ quantization -------------------------------
__device__ __forceinline__ void quant1(float v, int8_t& h8, int8_t& l8) {
    int q = __float2int_rn(v * 4096.0f);
    q = max(-32640, min(32639, q));
    int hi = (q + 128) >> 8;
    h8 = (int8_t)hi;
    l8 = (int8_t)(q - (hi << 8));
}

__global__ void quant_x_kernel(const float4* __restrict__ x, int n4) {
    int i = blockIdx.x * blockDim.x + threadIdx.x;
    if (i >= n4) return;
    float4 v = x[i];
    char4 h, l;
    quant1(v.x, (int8_t&)h.x, (int8_t&)l.x);
    quant1(v.y, (int8_t&)h.y, (int8_t&)l.y);
    quant1(v.z, (int8_t&)h.z, (int8_t&)l.z);
    quant1(v.w, (int8_t&)h.w, (int8_t&)l.w);
    reinterpret_cast<char4*>(g_A_hi)[i] = h;
    reinterpret_cast<char4*>(g_A_lo)[i] = l;
}

__global__ void sign_w_kernel(const float4* __restrict__ w, int n4) {
    int i = blockIdx.x * blockDim.x + threadIdx.x;
    if (i >= n4) return;
    float4 v = w[i];
    char4 s;
    s.x = (char)((v.x > 0.0f) - (v.x < 0.0f));
    s.y = (char)((v.y > 0.0f) - (v.y < 0.0f));
    s.z = (char)((v.z > 0.0f) - (v.z < 0.0f));
    s.w = (char)((v.w > 0.0f) - (v.w < 0.0f));
    reinterpret_cast<char4*>(g_S)[i] = s;
}

// ------------------------------- GEMM kernel -------------------------------
// CTA tile 128(M) x 128(N), K-step 128. 4-stage TMA pipeline (48 KB/stage).
// 256 threads = 8 warps in a 2(M) x 4(N) grid; warp tile 64 x 32.
// Both planes (hi/lo) computed in one CTA so B is loaded once.

static constexpr int STAGES      = 4;
static constexpr int STAGE_BYTES = 49152;          // 16K A_hi + 16K A_lo + 16K B
static constexpr int KITERS      = K_TOTAL / 128;  // 32
static constexpr int SMEM_DYN    = 1024 + 1024 + STAGES * STAGE_BYTES;

__global__ void __launch_bounds__(256, 1) ternary_gemm_kernel(
    const __grid_constant__ CUtensorMap tma_ahi,
    const __grid_constant__ CUtensorMap tma_alo,
    const __grid_constant__ CUtensorMap tma_b,
    float* __restrict__ out)
{
    extern __shared__ uint8_t smem_raw[];
    const uint32_t sb    = smem_u32(smem_raw);
    const uint32_t base  = (sb + 1023u) & ~1023u;
    const uint32_t FULLB = base;          // 4 x 8B mbarriers
    const uint32_t TILES = base + 1024;

    const int tid  = threadIdx.x;
    const int wid  = tid >> 5;
    const int lane = tid & 31;
    const int wm   = wid >> 2;            // 0..1
    const int wn   = wid & 3;             // 0..3

    // ---- tile mapping, GROUP_M=8 for L2 reuse ----
    constexpr int TILES_N = N_TOTAL / 128;   // 128
    constexpr int GROUP_M = 8;
    const int per_group = GROUP_M * TILES_N;
    const int grp = blockIdx.x / per_group;
    const int ing = blockIdx.x % per_group;
    const int mt_tile = grp * GROUP_M + (ing % GROUP_M);
    const int nt_tile = ing / GROUP_M;
    const int gm = mt_tile * 128;
    const int gn = nt_tile * 128;

    // ---- init barriers ----
    if (tid == 0) {
        #pragma unroll
        for (int s = 0; s < STAGES; s++) MBAR_INIT(FULLB + 8 * s, 1);
        FENCE_PROXY_ASYNC();
    }
    __syncthreads();

    // ---- prologue: fill stages 0..STAGES-2 ----
    if (tid == 0) {
        #pragma unroll
        for (int s = 0; s < STAGES - 1; s++) {
            MBAR_EXPECT_TX(FULLB + 8 * s, (uint32_t)STAGE_BYTES);
            const uint32_t tb = TILES + s * STAGE_BYTES;
            TMA_LOAD_2D(tb,         &tma_ahi, s * 128, gm, FULLB + 8 * s);
            TMA_LOAD_2D(tb + 16384, &tma_alo, s * 128, gm, FULLB + 8 * s);
            TMA_LOAD_2D(tb + 32768, &tma_b,   s * 128, gn, FULLB + 8 * s);
        }
    }

    // ---- per-lane ldmatrix address pieces (SW128: col16 ^= row&7) ----
    const int mi  = lane >> 3;      // matrix index 0..3
    const int r   = lane & 7;       // row within matrix
    const int hi2 = mi >> 1;
    const uint32_t a_row_off  = (uint32_t)(wm * 64 + (mi & 1) * 8 + r) * 128;
    const uint32_t b_row_off0 = (uint32_t)(wn * 32 + hi2 * 8 + r) * 128;
    const uint32_t b_row_off1 = b_row_off0 + 16 * 128;

    // ---- accumulators ----
    int ach[4][4][4], acl[4][4][4];
    #pragma unroll
    for (int a = 0; a < 4; a++)
        #pragma unroll
        for (int b = 0; b < 4; b++)
            #pragma unroll
            for (int c = 0; c < 4; c++) { ach[a][b][c] = 0; acl[a][b][c] = 0; }

    // ---- main loop ----
    for (int kt = 0; kt < KITERS; kt++) {
        const int s = kt & (STAGES - 1);
        const uint32_t ph = (uint32_t)((kt >> 2) & 1);
        MBAR_WAIT(FULLB + 8 * s, ph);
        __syncthreads();   // all warps done with slot (kt-1)&3; safe to refill

        if (tid == 0 && kt + STAGES - 1 < KITERS) {
            const int ns = (kt + STAGES - 1) & (STAGES - 1);
            MBAR_EXPECT_TX(FULLB + 8 * ns, (uint32_t)STAGE_BYTES);
            const uint32_t tb = TILES + ns * STAGE_BYTES;
            const int kx = (kt + STAGES - 1) * 128;
            TMA_LOAD_2D(tb,         &tma_ahi, kx, gm, FULLB + 8 * ns);
            TMA_LOAD_2D(tb + 16384, &tma_alo, kx, gm, FULLB + 8 * ns);
            TMA_LOAD_2D(tb + 32768, &tma_b,   kx, gn, FULLB + 8 * ns);
        }

        const uint32_t sa_hi = TILES + s * STAGE_BYTES;
        const uint32_t sa_lo = sa_hi + 16384;
        const uint32_t sbb   = sa_hi + 32768;

        #pragma unroll
        for (int kc = 0; kc < 4; kc++) {
            const uint32_t ax = (uint32_t)((((kc << 1) | hi2) ^ r) << 4);
            const uint32_t bx = (uint32_t)((((kc << 1) | (mi & 1)) ^ r) << 4);

            uint32_t ah[4][4], al[4][4], bf[4][2];
            #pragma unroll
            for (int mt = 0; mt < 4; mt++)
                LDSM4(ah[mt][0], ah[mt][1], ah[mt][2], ah[mt][3],
                      sa_hi + a_row_off + mt * 2048 + ax);
            #pragma unroll
            for (int mt = 0; mt < 4; mt++)
                LDSM4(al[mt][0], al[mt][1], al[mt][2], al[mt][3],
                      sa_lo + a_row_off + mt * 2048 + ax);
            LDSM4(bf[0][0], bf[0][1], bf[1][0], bf[1][1], sbb + b_row_off0 + bx);
            LDSM4(bf[2][0], bf[2][1], bf[3][0], bf[3][1], sbb + b_row_off1 + bx);

            #pragma unroll
            for (int mt = 0; mt < 4; mt++)
                #pragma unroll
                for (int nt = 0; nt < 4; nt++) {
                    MMA_S8(ach[mt][nt], ah[mt], bf[nt][0], bf[nt][1]);
                    MMA_S8(acl[mt][nt], al[mt], bf[nt][0], bf[nt][1]);
                }
        }
    }

    // ---- epilogue: out = (hi*256 + lo) / 4096 ----
    constexpr float SCL = 1.0f / 4096.0f;
    const int rbase = gm + wm * 64 + (lane >> 2);
    const int cbase = gn + wn * 32 + (lane & 3) * 2;
    #pragma unroll
    for (int mt = 0; mt < 4; mt++) {
        const int r0 = rbase + mt * 16;
        #pragma unroll
        for (int nt = 0; nt < 4; nt++) {
            const int c = cbase + nt * 8;
            float2 v;
            v.x = (float)((ach[mt][nt][0] << 8) + acl[mt][nt][0]) * SCL;
            v.y = (float)((ach[mt][nt][1] << 8) + acl[mt][nt][1]) * SCL;
            *reinterpret_cast<float2*>(out + (size_t)r0 * N_TOTAL + c) = v;
            v.x = (float)((ach[mt][nt][2] << 8) + acl[mt][nt][2]) * SCL;
            v.y = (float)((ach[mt][nt][3] << 8) + acl[mt][nt][3]) * SCL;
            *reinterpret_cast<float2*>(out + (size_t)(r0 + 8) * N_TOTAL + c) = v;
        }
    }
}

// ------------------------------- host side ---------------------------------
typedef CUresult (*encode_fn_t)(CUtensorMap*, CUtensorMapDataType, cuuint32_t,
                                void*, const cuuint64_t*, const cuuint64_t*,
                                const cuuint32_t*, const cuuint32_t*,
                                CUtensorMapInterleave, CUtensorMapSwizzle,
                                CUtensorMapL2promotion, CUtensorMapFloatOOBfill);

static void make_map_i8(CUtensorMap* m, void* ptr,
                        uint64_t inner, uint64_t outer,
                        uint32_t box_i, uint32_t box_o) {
    encode_fn_t fn = nullptr;
    cudaDriverEntryPointQueryResult st;
    cudaGetDriverEntryPointByVersion("cuTensorMapEncodeTiled", (void**)&fn,
                                     12000, cudaEnableDefault, &st);
    if (!fn) return;
    cuuint64_t dims[2]    = {inner, outer};
    cuuint64_t strides[1] = {inner};          // bytes (1B elements)
    cuuint32_t box[2]     = {box_i, box_o};
    cuuint32_t es[2]      = {1, 1};
    fn(m, CU_TENSOR_MAP_DATA_TYPE_UINT8, 2, ptr, dims, strides, box, es,
       CU_TENSOR_MAP_INTERLEAVE_NONE, CU_TENSOR_MAP_SWIZZLE_128B,
       CU_TENSOR_MAP_L2_PROMOTION_L2_128B, CU_TENSOR_MAP_FLOAT_OOB_FILL_NONE);
}

extern "C" void kernel_launch(void* const* d_in, const int* in_sizes, int n_in,
                              void* d_out, int out_size) {
    const float* x = (const float*)d_in[0];   // [2,4096,4096]
    const float* w = (const float*)d_in[1];   // [16384,4096]
    float* out = (float*)d_out;               // [2,4096,16384]

    {
        const int n4x = (M_TOTAL * K_TOTAL) / 4;
        quant_x_kernel<<<(n4x + 255) / 256, 256>>>((const float4*)x, n4x);
        const int n4w = (N_TOTAL * K_TOTAL) / 4;
        sign_w_kernel<<<(n4w + 255) / 256, 256>>>((const float4*)w, n4w);
    }

    void *p_hi = nullptr, *p_lo = nullptr, *p_s = nullptr;
    cudaGetSymbolAddress(&p_hi, g_A_hi);
    cudaGetSymbolAddress(&p_lo, g_A_lo);
    cudaGetSymbolAddress(&p_s,  g_S);

    CUtensorMap mA, mL, mB;
    make_map_i8(&mA, p_hi, K_TOTAL, M_TOTAL, 128, 128);
    make_map_i8(&mL, p_lo, K_TOTAL, M_TOTAL, 128, 128);
    make_map_i8(&mB, p_s,  K_TOTAL, N_TOTAL, 128, 128);

    cudaFuncSetAttribute(ternary_gemm_kernel,
                         cudaFuncAttributeMaxDynamicSharedMemorySize, SMEM_DYN);

    const int grid = (M_TOTAL / 128) * (N_TOTAL / 128);   // 64 * 128 = 8192
    ternary_gemm_kernel<<<grid, 256, SMEM_DYN>>>(mA, mL, mB, out);
}

// round 3
// speedup vs baseline: 1.0011x; 1.0011x over previous
#include <cuda_runtime.h>
#include <cuda.h>
#include <cstdint>

// ============================================================================
// TernaryLinear: out[m,n] = sum_k x[m,k] * sign(w[n,k])
//   M = 8192, N = 16384, K = 4096, fp32 in/out.
//
// Exact-integer split GEMM on mma.sync int8 tensor cores (tcgen05 unavailable:
// harness emits plain compute_103 PTX which rejects all tcgen05).
//   q = round(x*4096) in [-32640,32639]; q = hi*256 + lo (int8, exact)
//   S = sign(w) int8 (exact)
//   y = (256*(hi@S^T) + (lo@S^T)) / 4096   (s32 accumulation, exact)
// rel_err ~7e-5 (x-quantization only) — verified in round 2.
//
// Round-3 changes vs round 2 (14.35 ms):
//   * 512 threads / 16 warps, warp tile 32x32: 64 accs/thread (~115 regs,
//     no spill risk), 4 warps/SMSP for latency hiding  (was: 8 warps,
//     128 accs, ~200 regs, 2/SMSP)
//   * quant+sign fused into ONE prologue kernel so ncu -s5 -c1 captures the
//     GEMM launch instead of the prologue.
// ============================================================================

#define M_TOTAL 8192
#define K_TOTAL 4096
#define N_TOTAL 16384

// ------------------------- device scratch (no mallocs) ---------------------
__device__ __align__(1024) int8_t g_A_hi[(size_t)M_TOTAL * K_TOTAL];   // 32 MB
__device__ __align__(1024) int8_t g_A_lo[(size_t)M_TOTAL * K_TOTAL];   // 32 MB
__device__ __align__(1024) int8_t g_S[(size_t)N_TOTAL * K_TOTAL];      // 64 MB

// ------------------------------ PTX helpers --------------------------------
__device__ __forceinline__ uint32_t smem_u32(const void* p) {
    uint32_t a;
    asm("{ .reg .u64 t; cvta.to.shared.u64 t, %1; cvt.u32.u64 %0, t; }"
        : "=r"(a) : "l"(p));
    return a;
}

#define MBAR_INIT(addr, cnt) \
    asm volatile("mbarrier.init.shared.b64 [%0], %1;" :: "r"(addr), "r"(cnt) : "memory")

#define MBAR_EXPECT_TX(addr, bytes) \
    asm volatile("mbarrier.arrive.expect_tx.shared.b64 _, [%0], %1;" \
                 :: "r"(addr), "r"(bytes) : "memory")

#define MBAR_WAIT(addr, ph) do {                                              \
    asm volatile("{\n\t.reg .pred P1;\n\t"                                    \
        "WAIT_%=:\n\t"                                                        \
        "mbarrier.try_wait.parity.acquire.cta.shared::cta.b64 P1, [%0], %1, 0x989680;\n\t" \
        "@P1 bra.uni DONE_%=;\n\t"                                            \
        "bra.uni WAIT_%=;\n\t"                                                \
        "DONE_%=:\n\t}"                                                       \
        :: "r"(addr), "r"(ph) : "memory");                                    \
} while (0)

#define TMA_LOAD_2D(dst, map, cx, cy, mbar) \
    asm volatile("cp.async.bulk.tensor.2d.shared::cta.global.tile.mbarrier::complete_tx::bytes " \
                 "[%0], [%1, {%2, %3}], [%4];" \
                 :: "r"(dst), "l"(map), "r"(cx), "r"(cy), "r"(mbar) : "memory")

#define FENCE_PROXY_ASYNC() \
    asm volatile("fence.proxy.async.shared::cta;" ::: "memory")

#define LDSM4(r0, r1, r2, r3, addr)                                           \
    asm volatile("ldmatrix.sync.aligned.m8n8.x4.shared.b16 {%0,%1,%2,%3}, [%4];" \
        : "=r"(r0), "=r"(r1), "=r"(r2), "=r"(r3) : "r"(addr))

#define MMA_S8(d, a, b0, b1)                                                  \
    asm volatile("mma.sync.aligned.m16n8k32.row.col.s32.s8.s8.s32 "           \
        "{%0,%1,%2,%3}, {%4,%5,%6,%7}, {%8,%9}, {%0,%1,%2,%3};"               \
        : "+r"((d)[0]), "+r"((d)[1]), "+r"((d)[2]), "+r"((d)[3])              \
        : "r"((a)[0]), "r"((a)[1]), "r"((a)[2]), "r"((a)[3]),                 \
          "r"(b0), "r"(b1))

// -------------------- fused prologue: quant(x) + sign(w) -------------------
__device__ __forceinline__ void quant1(float v, int8_t& h8, int8_t& l8) {
    int q = __float2int_rn(v * 4096.0f);
    q = max(-32640, min(32639, q));
    int hi = (q + 128) >> 8;
    h8 = (int8_t)hi;
    l8 = (int8_t)(q - (hi << 8));
}

__global__ void prep_kernel(const float4* __restrict__ x,
                            const float4* __restrict__ w,
                            int n4x, int n4w) {
    int i = blockIdx.x * blockDim.x + threadIdx.x;
    if (i < n4x) {
        float4 v = x[i];
        char4 h, l;
        quant1(v.x, (int8_t&)h.x, (int8_t&)l.x);
        quant1(v.y, (int8_t&)h.y, (int8_t&)l.y);
        quant1(v.z, (int8_t&)h.z, (int8_t&)l.z);
        quant1(v.w, (int8_t&)h.w, (int8_t&)l.w);
        reinterpret_cast<char4*>(g_A_hi)[i] = h;
        reinterpret_cast<char4*>(g_A_lo)[i] = l;
    } else {
        int j = i - n4x;
        if (j < n4w) {
            float4 v = w[j];
            char4 s;
            s.x = (char)((v.x > 0.0f) - (v.x < 0.0f));
            s.y = (char)((v.y > 0.0f) - (v.y < 0.0f));
            s.z = (char)((v.z > 0.0f) - (v.z < 0.0f));
            s.w = (char)((v.w > 0.0f) - (v.w < 0.0f));
            reinterpret_cast<char4*>(g_S)[j] = s;
        }
    }
}

// ------------------------------- GEMM kernel -------------------------------
// CTA tile 128(M) x 128(N), K-step 128 B. 4-stage TMA pipeline (48 KB/stage).
// 512 threads = 16 warps, 4(M) x 4(N) warp grid; warp tile 32 x 32, both
// planes -> 64 s32 accumulators / thread.

static constexpr int STAGES      = 4;
static constexpr int STAGE_BYTES = 49152;          // 16K A_hi + 16K A_lo + 16K B
static constexpr int KITERS      = K_TOTAL / 128;  // 32
static constexpr int SMEM_DYN    = 1024 + 1024 + STAGES * STAGE_BYTES;

__global__ void __launch_bounds__(512, 1) ternary_gemm_kernel(
    const __grid_constant__ CUtensorMap tma_ahi,
    const __grid_constant__ CUtensorMap tma_alo,
    const __grid_constant__ CUtensorMap tma_b,
    float* __restrict__ out)
{
    extern __shared__ uint8_t smem_raw[];
    const uint32_t sb    = smem_u32(smem_raw);
    const uint32_t base  = (sb + 1023u) & ~1023u;
    const uint32_t FULLB = base;          // 4 x 8B mbarriers
    const uint32_t TILES = base + 1024;

    const int tid  = threadIdx.x;
    const int wid  = tid >> 5;
    const int lane = tid & 31;
    const int wm   = wid >> 2;            // 0..3
    const int wn   = wid & 3;             // 0..3

    // ---- tile mapping, GROUP_M=8 for L2 reuse ----
    constexpr int TILES_N = N_TOTAL / 128;   // 128
    constexpr int GROUP_M = 8;
    const int per_group = GROUP_M * TILES_N;
    const int grp = blockIdx.x / per_group;
    const int ing = blockIdx.x % per_group;
    const int mt_tile = grp * GROUP_M + (ing % GROUP_M);
    const int nt_tile = ing / GROUP_M;
    const int gm = mt_tile * 128;
    const int gn = nt_tile * 128;

    // ---- init barriers ----
    if (tid == 0) {
        #pragma unroll
        for (int s = 0; s < STAGES; s++) MBAR_INIT(FULLB + 8 * s, 1);
        FENCE_PROXY_ASYNC();
    }
    __syncthreads();

    // ---- prologue: fill stages 0..STAGES-2 ----
    if (tid == 0) {
        #pragma unroll
        for (int s = 0; s < STAGES - 1; s++) {
            MBAR_EXPECT_TX(FULLB + 8 * s, (uint32_t)STAGE_BYTES);
            const uint32_t tb = TILES + s * STAGE_BYTES;
            TMA_LOAD_2D(tb,         &tma_ahi, s * 128, gm, FULLB + 8 * s);
            TMA_LOAD_2D(tb + 16384, &tma_alo, s * 128, gm, FULLB + 8 * s);
            TMA_LOAD_2D(tb + 32768, &tma_b,   s * 128, gn, FULLB + 8 * s);
        }
    }

    // ---- per-lane ldmatrix address pieces (SW128 swizzle, verified R2) ----
    const int mi  = lane >> 3;      // matrix index 0..3
    const int r   = lane & 7;       // row within matrix
    const int hi2 = mi >> 1;
    const uint32_t a_row_off  = (uint32_t)(wm * 32 + (mi & 1) * 8 + r) * 128;
    const uint32_t b_row_off0 = (uint32_t)(wn * 32 + hi2 * 8 + r) * 128;
    const uint32_t b_row_off1 = b_row_off0 + 16 * 128;

    // ---- accumulators: [mt(2)][nt(4)][4] per plane = 64 regs ----
    int ach[2][4][4], acl[2][4][4];
    #pragma unroll
    for (int a = 0; a < 2; a++)
        #pragma unroll
        for (int b = 0; b < 4; b++)
            #pragma unroll
            for (int c = 0; c < 4; c++) { ach[a][b][c] = 0; acl[a][b][c] = 0; }

    // ---- main loop ----
    for (int kt = 0; kt < KITERS; kt++) {
        const int s = kt & (STAGES - 1);
        const uint32_t ph = (uint32_t)((kt >> 2) & 1);
        MBAR_WAIT(FULLB + 8 * s, ph);
        __syncthreads();   // all warps finished iter kt-1 -> its slot is free

        if (tid == 0 && kt + STAGES - 1 < KITERS) {
            const int ns = (kt + STAGES - 1) & (STAGES - 1);
            MBAR_EXPECT_TX(FULLB + 8 * ns, (uint32_t)STAGE_BYTES);
            const uint32_t tb = TILES + ns * STAGE_BYTES;
            const int kx = (kt + STAGES - 1) * 128;
            TMA_LOAD_2D(tb,         &tma_ahi, kx, gm, FULLB + 8 * ns);
            TMA_LOAD_2D(tb + 16384, &tma_alo, kx, gm, FULLB + 8 * ns);
            TMA_LOAD_2D(tb + 32768, &tma_b,   kx, gn, FULLB + 8 * ns);
        }

        const uint32_t sa_hi = TILES + s * STAGE_BYTES;
        const uint32_t sa_lo = sa_hi + 16384;
        const uint32_t sbb   = sa_hi + 32768;

        #pragma unroll
        for (int kc = 0; kc < 4; kc++) {
            const uint32_t ax = (uint32_t)((((kc << 1) | hi2) ^ r) << 4);
            const uint32_t bx = (uint32_t)((((kc << 1) | (mi & 1)) ^ r) << 4);

            uint32_t ah[2][4], al[2][4], bf[4][2];
            #pragma unroll
            for (int mt = 0; mt < 2; mt++)
                LDSM4(ah[mt][0], ah[mt][1], ah[mt][2], ah[mt][3],
                      sa_hi + a_row_off + mt * 2048 + ax);
            #pragma unroll
            for (int mt = 0; mt < 2; mt++)
                LDSM4(al[mt][0], al[mt][1], al[mt][2], al[mt][3],
                      sa_lo + a_row_off + mt * 2048 + ax);
            LDSM4(bf[0][0], bf[0][1], bf[1][0], bf[1][1], sbb + b_row_off0 + bx);
            LDSM4(bf[2][0], bf[2][1], bf[3][0], bf[3][1], sbb + b_row_off1 + bx);

            #pragma unroll
            for (int mt = 0; mt < 2; mt++)
                #pragma unroll
                for (int nt = 0; nt < 4; nt++) {
                    MMA_S8(ach[mt][nt], ah[mt], bf[nt][0], bf[nt][1]);
                    MMA_S8(acl[mt][nt], al[mt], bf[nt][0], bf[nt][1]);
                }
        }
    }

    // ---- epilogue: out = (hi*256 + lo) / 4096 ----
    constexpr float SCL = 1.0f / 4096.0f;
    const int rbase = gm + wm * 32 + (lane >> 2);
    const int cbase = gn + wn * 32 + (lane & 3) * 2;
    #pragma unroll
    for (int mt = 0; mt < 2; mt++) {
        const int r0 = rbase + mt * 16;
        #pragma unroll
        for (int nt = 0; nt < 4; nt++) {
            const int c = cbase + nt * 8;
            float2 v;
            v.x = (float)((ach[mt][nt][0] << 8) + acl[mt][nt][0]) * SCL;
            v.y = (float)((ach[mt][nt][1] << 8) + acl[mt][nt][1]) * SCL;
            *reinterpret_cast<float2*>(out + (size_t)r0 * N_TOTAL + c) = v;
            v.x = (float)((ach[mt][nt][2] << 8) + acl[mt][nt][2]) * SCL;
            v.y = (float)((ach[mt][nt][3] << 8) + acl[mt][nt][3]) * SCL;
            *reinterpret_cast<float2*>(out + (size_t)(r0 + 8) * N_TOTAL + c) = v;
        }
    }
}

// ------------------------------- host side ---------------------------------
typedef CUresult (*encode_fn_t)(CUtensorMap*, CUtensorMapDataType, cuuint32_t,
                                void*, const cuuint64_t*, const cuuint64_t*,
                                const cuuint32_t*, const cuuint32_t*,
                                CUtensorMapInterleave, CUtensorMapSwizzle,
                                CUtensorMapL2promotion, CUtensorMapFloatOOBfill);

static void make_map_i8(CUtensorMap* m, void* ptr,
                        uint64_t inner, uint64_t outer,
                        uint32_t box_i, uint32_t box_o) {
    encode_fn_t fn = nullptr;
    cudaDriverEntryPointQueryResult st;
    cudaGetDriverEntryPointByVersion("cuTensorMapEncodeTiled", (void**)&fn,
                                     12000, cudaEnableDefault, &st);
    if (!fn) return;
    cuuint64_t dims[2]    = {inner, outer};
    cuuint64_t strides[1] = {inner};          // bytes (1B elements)
    cuuint32_t box[2]     = {box_i, box_o};
    cuuint32_t es[2]      = {1, 1};
    fn(m, CU_TENSOR_MAP_DATA_TYPE_UINT8, 2, ptr, dims, strides, box, es,
       CU_TENSOR_MAP_INTERLEAVE_NONE, CU_TENSOR_MAP_SWIZZLE_128B,
       CU_TENSOR_MAP_L2_PROMOTION_L2_128B, CU_TENSOR_MAP_FLOAT_OOB_FILL_NONE);
}

extern "C" void kernel_launch(void* const* d_in, const int* in_sizes, int n_in,
                              void* d_out, int out_size) {
    const float* x = (const float*)d_in[0];   // [2,4096,4096]
    const float* w = (const float*)d_in[1];   // [16384,4096]
    float* out = (float*)d_out;               // [2,4096,16384]

    // fused prologue (1 launch -> ncu -s5 -c1 lands on the GEMM)
    {
        const int n4x = (M_TOTAL * K_TOTAL) / 4;
        const int n4w = (N_TOTAL * K_TOTAL) / 4;
        const int total = n4x + n4w;
        prep_kernel<<<(total + 255) / 256, 256>>>((const float4*)x,
                                                  (const float4*)w, n4x, n4w);
    }

    void *p_hi = nullptr, *p_lo = nullptr, *p_s = nullptr;
    cudaGetSymbolAddress(&p_hi, g_A_hi);
    cudaGetSymbolAddress(&p_lo, g_A_lo);
    cudaGetSymbolAddress(&p_s,  g_S);

    CUtensorMap mA, mL, mB;
    make_map_i8(&mA, p_hi, K_TOTAL, M_TOTAL, 128, 128);
    make_map_i8(&mL, p_lo, K_TOTAL, M_TOTAL, 128, 128);
    make_map_i8(&mB, p_s,  K_TOTAL, N_TOTAL, 128, 128);

    cudaFuncSetAttribute(ternary_gemm_kernel,
                         cudaFuncAttributeMaxDynamicSharedMemorySize, SMEM_DYN);

    const int grid = (M_TOTAL / 128) * (N_TOTAL / 128);   // 8192
    ternary_gemm_kernel<<<grid, 512, SMEM_DYN>>>(mA, mL, mB, out);
}

// round 4
// speedup vs baseline: 4.8841x; 4.8787x over previous
#include <cuda_runtime.h>
#include <cuda.h>
#include <cuda_fp16.h>
#include <cstdint>

// ============================================================================
// TernaryLinear: out[m,n] = sum_k x[m,k] * sign(w[n,k])
//   M = 8192, N = 16384, K = 4096, fp32 in/out.
//
// Round-4 strategy: SINGLE-plane fp16 GEMM on legacy mma.sync tensor cores.
//   A = fp16(x)        (error 2^-11 rel per element -> output rel_err ~1.2e-4)
//   B = sign(w) in fp16 (exact: -1, 0, +1)
//   y = A @ B^T with fp32 accumulation.
// vs round 3 (14.33 ms, tensor pipe 97.5% = legacy-mma HW floor): halves the
// total MAC count (one plane instead of hi/lo int8 split) at identical
// instruction count (m16n8k16.f16 = 2048 MACs/instr vs m16n8k32.s8 = 4096).
// If the legacy unit is per-MAC-bound this is ~2x; if per-instruction-bound
// it is neutral and proves the floor. tcgen05 remains unavailable (harness
// compiles via compute_103 PTX which rejects all tcgen05/TMEM ops).
// ============================================================================

#define M_TOTAL 8192
#define K_TOTAL 4096
#define N_TOTAL 16384

// ------------------------- device scratch (no mallocs) ---------------------
__device__ __align__(1024) __half g_A[(size_t)M_TOTAL * K_TOTAL];   // 64 MB
__device__ __align__(1024) __half g_B[(size_t)N_TOTAL * K_TOTAL];   // 128 MB

// ------------------------------ PTX helpers --------------------------------
__device__ __forceinline__ uint32_t smem_u32(const void* p) {
    uint32_t a;
    asm("{ .reg .u64 t; cvta.to.shared.u64 t, %1; cvt.u32.u64 %0, t; }"
        : "=r"(a) : "l"(p));
    return a;
}

#define MBAR_INIT(addr, cnt) \
    asm volatile("mbarrier.init.shared.b64 [%0], %1;" :: "r"(addr), "r"(cnt) : "memory")

#define MBAR_EXPECT_TX(addr, bytes) \
    asm volatile("mbarrier.arrive.expect_tx.shared.b64 _, [%0], %1;" \
                 :: "r"(addr), "r"(bytes) : "memory")

#define MBAR_WAIT(addr, ph) do {                                              \
    asm volatile("{\n\t.reg .pred P1;\n\t"                                    \
        "WAIT_%=:\n\t"                                                        \
        "mbarrier.try_wait.parity.acquire.cta.shared::cta.b64 P1, [%0], %1, 0x989680;\n\t" \
        "@P1 bra.uni DONE_%=;\n\t"                                            \
        "bra.uni WAIT_%=;\n\t"                                                \
        "DONE_%=:\n\t}"                                                       \
        :: "r"(addr), "r"(ph) : "memory");                                    \
} while (0)

#define TMA_LOAD_2D(dst, map, cx, cy, mbar) \
    asm volatile("cp.async.bulk.tensor.2d.shared::cta.global.tile.mbarrier::complete_tx::bytes " \
                 "[%0], [%1, {%2, %3}], [%4];" \
                 :: "r"(dst), "l"(map), "r"(cx), "r"(cy), "r"(mbar) : "memory")

#define FENCE_PROXY_ASYNC() \
    asm volatile("fence.proxy.async.shared::cta;" ::: "memory")

#define LDSM4(r0, r1, r2, r3, addr)                                           \
    asm volatile("ldmatrix.sync.aligned.m8n8.x4.shared.b16 {%0,%1,%2,%3}, [%4];" \
        : "=r"(r0), "=r"(r1), "=r"(r2), "=r"(r3) : "r"(addr))

// fp16 mma, fp32 accumulate
#define MMA_F16(d, a, b0, b1)                                                 \
    asm volatile("mma.sync.aligned.m16n8k16.row.col.f32.f16.f16.f32 "         \
        "{%0,%1,%2,%3}, {%4,%5,%6,%7}, {%8,%9}, {%0,%1,%2,%3};"               \
        : "+f"((d)[0]), "+f"((d)[1]), "+f"((d)[2]), "+f"((d)[3])              \
        : "r"((a)[0]), "r"((a)[1]), "r"((a)[2]), "r"((a)[3]),                 \
          "r"(b0), "r"(b1))

// -------------------- fused prologue: x->fp16, sign(w)->fp16 ---------------
__global__ void prep_kernel(const float4* __restrict__ x,
                            const float4* __restrict__ w,
                            int n4x, int n4w) {
    int i = blockIdx.x * blockDim.x + threadIdx.x;
    if (i < n4x) {
        float4 v = x[i];
        __half2* dst = reinterpret_cast<__half2*>(g_A) + (size_t)i * 2;
        dst[0] = __floats2half2_rn(v.x, v.y);
        dst[1] = __floats2half2_rn(v.z, v.w);
    } else {
        int j = i - n4x;
        if (j < n4w) {
            float4 v = w[j];
            float sx = (float)((v.x > 0.0f) - (v.x < 0.0f));
            float sy = (float)((v.y > 0.0f) - (v.y < 0.0f));
            float sz = (float)((v.z > 0.0f) - (v.z < 0.0f));
            float sw = (float)((v.w > 0.0f) - (v.w < 0.0f));
            __half2* dst = reinterpret_cast<__half2*>(g_B) + (size_t)j * 2;
            dst[0] = __floats2half2_rn(sx, sy);
            dst[1] = __floats2half2_rn(sz, sw);
        }
    }
}

// ------------------------------- GEMM kernel -------------------------------
// CTA tile 128(M) x 128(N), K-step 64 halves (128 B rows). 4-stage TMA
// pipeline (32 KB/stage). 512 threads = 16 warps (4x4); warp tile 32x32,
// 32 f32 accumulators / thread.

static constexpr int STAGES      = 4;
static constexpr int STAGE_BYTES = 32768;          // 16K A + 16K B
static constexpr int KITERS      = K_TOTAL / 64;   // 64 chunks of 64 halves
static constexpr int SMEM_DYN    = 1024 + 1024 + STAGES * STAGE_BYTES;

__global__ void __launch_bounds__(512, 1) ternary_gemm_kernel(
    const __grid_constant__ CUtensorMap tma_a,
    const __grid_constant__ CUtensorMap tma_b,
    float* __restrict__ out)
{
    extern __shared__ uint8_t smem_raw[];
    const uint32_t sb    = smem_u32(smem_raw);
    const uint32_t base  = (sb + 1023u) & ~1023u;
    const uint32_t FULLB = base;          // 4 x 8B mbarriers
    const uint32_t TILES = base + 1024;

    const int tid  = threadIdx.x;
    const int wid  = tid >> 5;
    const int lane = tid & 31;
    const int wm   = wid >> 2;            // 0..3
    const int wn   = wid & 3;             // 0..3

    // ---- tile mapping, GROUP_M=8 for L2 reuse ----
    constexpr int TILES_N = N_TOTAL / 128;   // 128
    constexpr int GROUP_M = 8;
    const int per_group = GROUP_M * TILES_N;
    const int grp = blockIdx.x / per_group;
    const int ing = blockIdx.x % per_group;
    const int mt_tile = grp * GROUP_M + (ing % GROUP_M);
    const int nt_tile = ing / GROUP_M;
    const int gm = mt_tile * 128;
    const int gn = nt_tile * 128;

    // ---- init barriers ----
    if (tid == 0) {
        #pragma unroll
        for (int s = 0; s < STAGES; s++) MBAR_INIT(FULLB + 8 * s, 1);
        FENCE_PROXY_ASYNC();
    }
    __syncthreads();

    // ---- prologue: fill stages 0..STAGES-2 (coords in fp16 elements) ----
    if (tid == 0) {
        #pragma unroll
        for (int s = 0; s < STAGES - 1; s++) {
            MBAR_EXPECT_TX(FULLB + 8 * s, (uint32_t)STAGE_BYTES);
            const uint32_t tb = TILES + s * STAGE_BYTES;
            TMA_LOAD_2D(tb,         &tma_a, s * 64, gm, FULLB + 8 * s);
            TMA_LOAD_2D(tb + 16384, &tma_b, s * 64, gn, FULLB + 8 * s);
        }
    }

    // ---- per-lane ldmatrix address pieces (SW128, verified in R2/R3) ----
    // Rows are 128 B (= 64 halves). Byte geometry identical to the s8 case:
    // fp16 k16 fragment = 32 bytes = two 16B units, same as s8 k32.
    const int mi  = lane >> 3;      // ldmatrix matrix index 0..3
    const int r   = lane & 7;       // row within 8x8 matrix
    const int hi2 = mi >> 1;
    const uint32_t a_row_off  = (uint32_t)(wm * 32 + (mi & 1) * 8 + r) * 128;
    const uint32_t b_row_off0 = (uint32_t)(wn * 32 + hi2 * 8 + r) * 128;
    const uint32_t b_row_off1 = b_row_off0 + 16 * 128;

    // ---- accumulators: [mt(2)][nt(4)][4] f32 = 32 regs ----
    float acc[2][4][4];
    #pragma unroll
    for (int a = 0; a < 2; a++)
        #pragma unroll
        for (int b = 0; b < 4; b++)
            #pragma unroll
            for (int c = 0; c < 4; c++) acc[a][b][c] = 0.0f;

    // ---- main loop: 64 chunks of k=64 halves ----
    for (int kt = 0; kt < KITERS; kt++) {
        const int s = kt & (STAGES - 1);
        const uint32_t ph = (uint32_t)((kt >> 2) & 1);
        MBAR_WAIT(FULLB + 8 * s, ph);
        __syncthreads();   // all warps finished iter kt-1 -> its slot is free

        if (tid == 0 && kt + STAGES - 1 < KITERS) {
            const int ns = (kt + STAGES - 1) & (STAGES - 1);
            MBAR_EXPECT_TX(FULLB + 8 * ns, (uint32_t)STAGE_BYTES);
            const uint32_t tb = TILES + ns * STAGE_BYTES;
            const int kx = (kt + STAGES - 1) * 64;
            TMA_LOAD_2D(tb,         &tma_a, kx, gm, FULLB + 8 * ns);
            TMA_LOAD_2D(tb + 16384, &tma_b, kx, gn, FULLB + 8 * ns);
        }

        const uint32_t sa  = TILES + s * STAGE_BYTES;
        const uint32_t sbb = sa + 16384;

        #pragma unroll
        for (int kc = 0; kc < 4; kc++) {   // 4 x k16 per 128B chunk
            const uint32_t ax = (uint32_t)((((kc << 1) | hi2) ^ r) << 4);
            const uint32_t bx = (uint32_t)((((kc << 1) | (mi & 1)) ^ r) << 4);

            uint32_t af[2][4], bf[4][2];
            #pragma unroll
            for (int mt = 0; mt < 2; mt++)
                LDSM4(af[mt][0], af[mt][1], af[mt][2], af[mt][3],
                      sa + a_row_off + mt * 2048 + ax);
            LDSM4(bf[0][0], bf[0][1], bf[1][0], bf[1][1], sbb + b_row_off0 + bx);
            LDSM4(bf[2][0], bf[2][1], bf[3][0], bf[3][1], sbb + b_row_off1 + bx);

            #pragma unroll
            for (int mt = 0; mt < 2; mt++)
                #pragma unroll
                for (int nt = 0; nt < 4; nt++)
                    MMA_F16(acc[mt][nt], af[mt], bf[nt][0], bf[nt][1]);
        }
    }

    // ---- epilogue: accumulators ARE the answer (no scaling) ----
    const int rbase = gm + wm * 32 + (lane >> 2);
    const int cbase = gn + wn * 32 + (lane & 3) * 2;
    #pragma unroll
    for (int mt = 0; mt < 2; mt++) {
        const int r0 = rbase + mt * 16;
        #pragma unroll
        for (int nt = 0; nt < 4; nt++) {
            const int c = cbase + nt * 8;
            float2 v;
            v.x = acc[mt][nt][0];
            v.y = acc[mt][nt][1];
            *reinterpret_cast<float2*>(out + (size_t)r0 * N_TOTAL + c) = v;
            v.x = acc[mt][nt][2];
            v.y = acc[mt][nt][3];
            *reinterpret_cast<float2*>(out + (size_t)(r0 + 8) * N_TOTAL + c) = v;
        }
    }
}

// ------------------------------- host side ---------------------------------
typedef CUresult (*encode_fn_t)(CUtensorMap*, CUtensorMapDataType, cuuint32_t,
                                void*, const cuuint64_t*, const cuuint64_t*,
                                const cuuint32_t*, const cuuint32_t*,
                                CUtensorMapInterleave, CUtensorMapSwizzle,
                                CUtensorMapL2promotion, CUtensorMapFloatOOBfill);

static void make_map_f16(CUtensorMap* m, void* ptr,
                         uint64_t inner, uint64_t outer,
                         uint32_t box_i, uint32_t box_o) {
    encode_fn_t fn = nullptr;
    cudaDriverEntryPointQueryResult st;
    cudaGetDriverEntryPointByVersion("cuTensorMapEncodeTiled", (void**)&fn,
                                     12000, cudaEnableDefault, &st);
    if (!fn) return;
    cuuint64_t dims[2]    = {inner, outer};
    cuuint64_t strides[1] = {inner * 2};      // bytes (fp16)
    cuuint32_t box[2]     = {box_i, box_o};
    cuuint32_t es[2]      = {1, 1};
    fn(m, CU_TENSOR_MAP_DATA_TYPE_UINT16, 2, ptr, dims, strides, box, es,
       CU_TENSOR_MAP_INTERLEAVE_NONE, CU_TENSOR_MAP_SWIZZLE_128B,
       CU_TENSOR_MAP_L2_PROMOTION_L2_128B, CU_TENSOR_MAP_FLOAT_OOB_FILL_NONE);
}

extern "C" void kernel_launch(void* const* d_in, const int* in_sizes, int n_in,
                              void* d_out, int out_size) {
    const float* x = (const float*)d_in[0];   // [2,4096,4096]
    const float* w = (const float*)d_in[1];   // [16384,4096]
    float* out = (float*)d_out;               // [2,4096,16384]

    // fused prologue (1 launch so ncu -s5 -c1 lands on the GEMM)
    {
        const int n4x = (M_TOTAL * K_TOTAL) / 4;
        const int n4w = (N_TOTAL * K_TOTAL) / 4;
        const int total = n4x + n4w;
        prep_kernel<<<(total + 255) / 256, 256>>>((const float4*)x,
                                                  (const float4*)w, n4x, n4w);
    }

    void *p_a = nullptr, *p_b = nullptr;
    cudaGetSymbolAddress(&p_a, g_A);
    cudaGetSymbolAddress(&p_b, g_B);

    CUtensorMap mA, mB;
    make_map_f16(&mA, p_a, K_TOTAL, M_TOTAL, 64, 128);
    make_map_f16(&mB, p_b, K_TOTAL, N_TOTAL, 64, 128);

    cudaFuncSetAttribute(ternary_gemm_kernel,
                         cudaFuncAttributeMaxDynamicSharedMemorySize, SMEM_DYN);

    const int grid = (M_TOTAL / 128) * (N_TOTAL / 128);   // 8192
    ternary_gemm_kernel<<<grid, 512, SMEM_DYN>>>(mA, mB, out);
}

// round 5
// speedup vs baseline: 6.2385x; 1.2773x over previous
#include <cuda_runtime.h>
#include <cuda.h>
#include <cuda_fp16.h>
#include <cstdint>

// ============================================================================
// TernaryLinear: out[m,n] = sum_k x[m,k] * sign(w[n,k])
//   M = 8192, N = 16384, K = 4096, fp32 in/out.
//
// fp16 single-plane GEMM on legacy mma.sync (tcgen05 unavailable: harness
// emits plain compute_103 PTX). A = fp16(x), B = sign(w) exact in fp16,
// fp32 accumulation. rel_err ~2.1e-4 (verified round 4).
//
// Round-5 change vs round 4 (2.94 ms, tensor=63.6% / L1=65.7% co-bound):
//   * warp tile 32x32 -> 64x64 (CTA 256x128, 8 warps 4x2, 256 threads):
//     LDSM per MMA halves (0.5 -> 0.25), so the smem crossbar stops
//     co-binding with the tensor pipe. Target: tensor ~90%+.
// ============================================================================

#define M_TOTAL 8192
#define K_TOTAL 4096
#define N_TOTAL 16384

// ------------------------- device scratch (no mallocs) ---------------------
__device__ __align__(1024) __half g_A[(size_t)M_TOTAL * K_TOTAL];   // 64 MB
__device__ __align__(1024) __half g_B[(size_t)N_TOTAL * K_TOTAL];   // 128 MB

// ------------------------------ PTX helpers --------------------------------
__device__ __forceinline__ uint32_t smem_u32(const void* p) {
    uint32_t a;
    asm("{ .reg .u64 t; cvta.to.shared.u64 t, %1; cvt.u32.u64 %0, t; }"
        : "=r"(a) : "l"(p));
    return a;
}

#define MBAR_INIT(addr, cnt) \
    asm volatile("mbarrier.init.shared.b64 [%0], %1;" :: "r"(addr), "r"(cnt) : "memory")

#define MBAR_EXPECT_TX(addr, bytes) \
    asm volatile("mbarrier.arrive.expect_tx.shared.b64 _, [%0], %1;" \
                 :: "r"(addr), "r"(bytes) : "memory")

#define MBAR_WAIT(addr, ph) do {                                              \
    asm volatile("{\n\t.reg .pred P1;\n\t"                                    \
        "WAIT_%=:\n\t"                                                        \
        "mbarrier.try_wait.parity.acquire.cta.shared::cta.b64 P1, [%0], %1, 0x989680;\n\t" \
        "@P1 bra.uni DONE_%=;\n\t"                                            \
        "bra.uni WAIT_%=;\n\t"                                                \
        "DONE_%=:\n\t}"                                                       \
        :: "r"(addr), "r"(ph) : "memory");                                    \
} while (0)

#define TMA_LOAD_2D(dst, map, cx, cy, mbar) \
    asm volatile("cp.async.bulk.tensor.2d.shared::cta.global.tile.mbarrier::complete_tx::bytes " \
                 "[%0], [%1, {%2, %3}], [%4];" \
                 :: "r"(dst), "l"(map), "r"(cx), "r"(cy), "r"(mbar) : "memory")

#define FENCE_PROXY_ASYNC() \
    asm volatile("fence.proxy.async.shared::cta;" ::: "memory")

#define LDSM4(r0, r1, r2, r3, addr)                                           \
    asm volatile("ldmatrix.sync.aligned.m8n8.x4.shared.b16 {%0,%1,%2,%3}, [%4];" \
        : "=r"(r0), "=r"(r1), "=r"(r2), "=r"(r3) : "r"(addr))

#define MMA_F16(d, a, b0, b1)                                                 \
    asm volatile("mma.sync.aligned.m16n8k16.row.col.f32.f16.f16.f32 "         \
        "{%0,%1,%2,%3}, {%4,%5,%6,%7}, {%8,%9}, {%0,%1,%2,%3};"               \
        : "+f"((d)[0]), "+f"((d)[1]), "+f"((d)[2]), "+f"((d)[3])              \
        : "r"((a)[0]), "r"((a)[1]), "r"((a)[2]), "r"((a)[3]),                 \
          "r"(b0), "r"(b1))

// -------------------- fused prologue: x->fp16, sign(w)->fp16 ---------------
__global__ void prep_kernel(const float4* __restrict__ x,
                            const float4* __restrict__ w,
                            int n4x, int n4w) {
    int i = blockIdx.x * blockDim.x + threadIdx.x;
    if (i < n4x) {
        float4 v = x[i];
        __half2* dst = reinterpret_cast<__half2*>(g_A) + (size_t)i * 2;
        dst[0] = __floats2half2_rn(v.x, v.y);
        dst[1] = __floats2half2_rn(v.z, v.w);
    } else {
        int j = i - n4x;
        if (j < n4w) {
            float4 v = w[j];
            float sx = (float)((v.x > 0.0f) - (v.x < 0.0f));
            float sy = (float)((v.y > 0.0f) - (v.y < 0.0f));
            float sz = (float)((v.z > 0.0f) - (v.z < 0.0f));
            float sw = (float)((v.w > 0.0f) - (v.w < 0.0f));
            __half2* dst = reinterpret_cast<__half2*>(g_B) + (size_t)j * 2;
            dst[0] = __floats2half2_rn(sx, sy);
            dst[1] = __floats2half2_rn(sz, sw);
        }
    }
}

// ------------------------------- GEMM kernel -------------------------------
// CTA tile 256(M) x 128(N), K-step 64 halves (128 B rows). 4-stage TMA
// pipeline (48 KB/stage). 256 threads = 8 warps (4x2); warp tile 64x64,
// 128 f32 accumulators / thread.

static constexpr int STAGES      = 4;
static constexpr int A_STG      = 32768;           // 256 rows x 128 B
static constexpr int B_STG      = 16384;           // 128 rows x 128 B
static constexpr int STAGE_BYTES = A_STG + B_STG;  // 48 KB
static constexpr int KITERS      = K_TOTAL / 64;   // 64
static constexpr int SMEM_DYN    = 1024 + 1024 + STAGES * STAGE_BYTES;

__global__ void __launch_bounds__(256, 1) ternary_gemm_kernel(
    const __grid_constant__ CUtensorMap tma_a,
    const __grid_constant__ CUtensorMap tma_b,
    float* __restrict__ out)
{
    extern __shared__ uint8_t smem_raw[];
    const uint32_t sb    = smem_u32(smem_raw);
    const uint32_t base  = (sb + 1023u) & ~1023u;
    const uint32_t FULLB = base;          // 4 x 8B mbarriers
    const uint32_t TILES = base + 1024;

    const int tid  = threadIdx.x;
    const int wid  = tid >> 5;
    const int lane = tid & 31;
    const int wm   = wid >> 1;            // 0..3  (M)
    const int wn   = wid & 1;             // 0..1  (N)

    // ---- tile mapping, GROUP_M=8 for L2 reuse ----
    constexpr int TILES_N = N_TOTAL / 128;   // 128
    constexpr int GROUP_M = 8;               // of 32 M-tiles
    const int per_group = GROUP_M * TILES_N;
    const int grp = blockIdx.x / per_group;
    const int ing = blockIdx.x % per_group;
    const int mt_tile = grp * GROUP_M + (ing % GROUP_M);
    const int nt_tile = ing / GROUP_M;
    const int gm = mt_tile * 256;
    const int gn = nt_tile * 128;

    // ---- init barriers ----
    if (tid == 0) {
        #pragma unroll
        for (int s = 0; s < STAGES; s++) MBAR_INIT(FULLB + 8 * s, 1);
        FENCE_PROXY_ASYNC();
    }
    __syncthreads();

    // ---- prologue: fill stages 0..STAGES-2 ----
    if (tid == 0) {
        #pragma unroll
        for (int s = 0; s < STAGES - 1; s++) {
            MBAR_EXPECT_TX(FULLB + 8 * s, (uint32_t)STAGE_BYTES);
            const uint32_t tb = TILES + s * STAGE_BYTES;
            TMA_LOAD_2D(tb,         &tma_a, s * 64, gm, FULLB + 8 * s);
            TMA_LOAD_2D(tb + A_STG, &tma_b, s * 64, gn, FULLB + 8 * s);
        }
    }

    // ---- per-lane ldmatrix address pieces (SW128 layout, verified R2-R4) ---
    const int mi  = lane >> 3;      // matrix index 0..3
    const int r   = lane & 7;       // row within 8x8 matrix
    const int hi2 = mi >> 1;
    const uint32_t a_row_off = (uint32_t)(wm * 64 + (mi & 1) * 8 + r) * 128;
    const uint32_t b_row_off = (uint32_t)(wn * 64 + hi2 * 8 + r) * 128;

    // ---- accumulators: [mt(4)][nt(8)][4] f32 = 128 regs ----
    float acc[4][8][4];
    #pragma unroll
    for (int a = 0; a < 4; a++)
        #pragma unroll
        for (int b = 0; b < 8; b++)
            #pragma unroll
            for (int c = 0; c < 4; c++) acc[a][b][c] = 0.0f;

    // ---- main loop: 64 chunks of k=64 halves ----
    for (int kt = 0; kt < KITERS; kt++) {
        const int s = kt & (STAGES - 1);
        const uint32_t ph = (uint32_t)((kt >> 2) & 1);
        MBAR_WAIT(FULLB + 8 * s, ph);
        __syncthreads();   // all warps finished iter kt-1 -> its slot is free

        if (tid == 0 && kt + STAGES - 1 < KITERS) {
            const int ns = (kt + STAGES - 1) & (STAGES - 1);
            MBAR_EXPECT_TX(FULLB + 8 * ns, (uint32_t)STAGE_BYTES);
            const uint32_t tb = TILES + ns * STAGE_BYTES;
            const int kx = (kt + STAGES - 1) * 64;
            TMA_LOAD_2D(tb,         &tma_a, kx, gm, FULLB + 8 * ns);
            TMA_LOAD_2D(tb + A_STG, &tma_b, kx, gn, FULLB + 8 * ns);
        }

        const uint32_t sa  = TILES + s * STAGE_BYTES;
        const uint32_t sbb = sa + A_STG;

        #pragma unroll
        for (int kc = 0; kc < 4; kc++) {   // 4 x k16 per 128B chunk
            const uint32_t ax = (uint32_t)((((kc << 1) | hi2) ^ r) << 4);
            const uint32_t bx = (uint32_t)((((kc << 1) | (mi & 1)) ^ r) << 4);

            uint32_t af[4][4], bf[8][2];
            #pragma unroll
            for (int mt = 0; mt < 4; mt++)
                LDSM4(af[mt][0], af[mt][1], af[mt][2], af[mt][3],
                      sa + a_row_off + mt * 2048 + ax);
            #pragma unroll
            for (int j = 0; j < 4; j++)
                LDSM4(bf[2 * j][0], bf[2 * j][1], bf[2 * j + 1][0], bf[2 * j + 1][1],
                      sbb + b_row_off + j * 2048 + bx);

            #pragma unroll
            for (int mt = 0; mt < 4; mt++)
                #pragma unroll
                for (int nt = 0; nt < 8; nt++)
                    MMA_F16(acc[mt][nt], af[mt], bf[nt][0], bf[nt][1]);
        }
    }

    // ---- epilogue ----
    const int rbase = gm + wm * 64 + (lane >> 2);
    const int cbase = gn + wn * 64 + (lane & 3) * 2;
    #pragma unroll
    for (int mt = 0; mt < 4; mt++) {
        const int r0 = rbase + mt * 16;
        #pragma unroll
        for (int nt = 0; nt < 8; nt++) {
            const int c = cbase + nt * 8;
            float2 v;
            v.x = acc[mt][nt][0];
            v.y = acc[mt][nt][1];
            *reinterpret_cast<float2*>(out + (size_t)r0 * N_TOTAL + c) = v;
            v.x = acc[mt][nt][2];
            v.y = acc[mt][nt][3];
            *reinterpret_cast<float2*>(out + (size_t)(r0 + 8) * N_TOTAL + c) = v;
        }
    }
}

// ------------------------------- host side ---------------------------------
typedef CUresult (*encode_fn_t)(CUtensorMap*, CUtensorMapDataType, cuuint32_t,
                                void*, const cuuint64_t*, const cuuint64_t*,
                                const cuuint32_t*, const cuuint32_t*,
                                CUtensorMapInterleave, CUtensorMapSwizzle,
                                CUtensorMapL2promotion, CUtensorMapFloatOOBfill);

static void make_map_f16(CUtensorMap* m, void* ptr,
                         uint64_t inner, uint64_t outer,
                         uint32_t box_i, uint32_t box_o) {
    encode_fn_t fn = nullptr;
    cudaDriverEntryPointQueryResult st;
    cudaGetDriverEntryPointByVersion("cuTensorMapEncodeTiled", (void**)&fn,
                                     12000, cudaEnableDefault, &st);
    if (!fn) return;
    cuuint64_t dims[2]    = {inner, outer};
    cuuint64_t strides[1] = {inner * 2};      // bytes (fp16)
    cuuint32_t box[2]     = {box_i, box_o};
    cuuint32_t es[2]      = {1, 1};
    fn(m, CU_TENSOR_MAP_DATA_TYPE_UINT16, 2, ptr, dims, strides, box, es,
       CU_TENSOR_MAP_INTERLEAVE_NONE, CU_TENSOR_MAP_SWIZZLE_128B,
       CU_TENSOR_MAP_L2_PROMOTION_L2_128B, CU_TENSOR_MAP_FLOAT_OOB_FILL_NONE);
}

extern "C" void kernel_launch(void* const* d_in, const int* in_sizes, int n_in,
                              void* d_out, int out_size) {
    const float* x = (const float*)d_in[0];   // [2,4096,4096]
    const float* w = (const float*)d_in[1];   // [16384,4096]
    float* out = (float*)d_out;               // [2,4096,16384]

    // fused prologue (1 launch so ncu -s5 -c1 lands on the GEMM)
    {
        const int n4x = (M_TOTAL * K_TOTAL) / 4;
        const int n4w = (N_TOTAL * K_TOTAL) / 4;
        const int total = n4x + n4w;
        prep_kernel<<<(total + 255) / 256, 256>>>((const float4*)x,
                                                  (const float4*)w, n4x, n4w);
    }

    void *p_a = nullptr, *p_b = nullptr;
    cudaGetSymbolAddress(&p_a, g_A);
    cudaGetSymbolAddress(&p_b, g_B);

    CUtensorMap mA, mB;
    make_map_f16(&mA, p_a, K_TOTAL, M_TOTAL, 64, 256);
    make_map_f16(&mB, p_b, K_TOTAL, N_TOTAL, 64, 128);

    cudaFuncSetAttribute(ternary_gemm_kernel,
                         cudaFuncAttributeMaxDynamicSharedMemorySize, SMEM_DYN);

    const int grid = (M_TOTAL / 256) * (N_TOTAL / 128);   // 32 * 128 = 4096
    ternary_gemm_kernel<<<grid, 256, SMEM_DYN>>>(mA, mB, out);
}

// round 6
// speedup vs baseline: 6.8892x; 1.1043x over previous
#include <cuda_runtime.h>
#include <cuda.h>
#include <cuda_fp16.h>
#include <cstdint>

// ============================================================================
// TernaryLinear: out[m,n] = sum_k x[m,k] * sign(w[n,k])
//   M = 8192, N = 16384, K = 4096, fp32 in/out.
//
// fp16 single-plane GEMM on legacy mma.sync (tcgen05 unavailable: harness
// emits plain compute_103 PTX). A = fp16(x), B = sign(w) exact in fp16,
// fp32 accumulation. rel_err ~2.1e-4 (verified rounds 4-5).
//
// Round-6 change vs round 5 (2.30 ms, tensor=82%):
//   * kill the 64 per-k-iter __syncthreads: per-stage EMPTY mbarriers
//     (count=8, one elected lane/warp) + producer waits EMPTY (relaxed)
//     before TMA refill. Warps skew freely across the 4-stage ring instead
//     of full-CTA lockstep. Target tensor ~90%+ (HMMA floor ~1.78 ms).
// ============================================================================

#define M_TOTAL 8192
#define K_TOTAL 4096
#define N_TOTAL 16384

// ------------------------- device scratch (no mallocs) ---------------------
__device__ __align__(1024) __half g_A[(size_t)M_TOTAL * K_TOTAL];   // 64 MB
__device__ __align__(1024) __half g_B[(size_t)N_TOTAL * K_TOTAL];   // 128 MB

// ------------------------------ PTX helpers --------------------------------
__device__ __forceinline__ uint32_t smem_u32(const void* p) {
    uint32_t a;
    asm("{ .reg .u64 t; cvta.to.shared.u64 t, %1; cvt.u32.u64 %0, t; }"
        : "=r"(a) : "l"(p));
    return a;
}

#define MBAR_INIT(addr, cnt) \
    asm volatile("mbarrier.init.shared.b64 [%0], %1;" :: "r"(addr), "r"(cnt) : "memory")

#define MBAR_EXPECT_TX(addr, bytes) \
    asm volatile("mbarrier.arrive.expect_tx.shared.b64 _, [%0], %1;" \
                 :: "r"(addr), "r"(bytes) : "memory")

#define MBAR_ARRIVE(addr) \
    asm volatile("mbarrier.arrive.shared.b64 _, [%0];" :: "r"(addr) : "memory")

#define MBAR_WAIT(addr, ph) do {                                              \
    asm volatile("{\n\t.reg .pred P1;\n\t"                                    \
        "WAIT_%=:\n\t"                                                        \
        "mbarrier.try_wait.parity.acquire.cta.shared::cta.b64 P1, [%0], %1, 0x989680;\n\t" \
        "@P1 bra.uni DONE_%=;\n\t"                                            \
        "bra.uni WAIT_%=;\n\t"                                                \
        "DONE_%=:\n\t}"                                                       \
        :: "r"(addr), "r"(ph) : "memory");                                    \
} while (0)

// relaxed: post-wait accesses are async-proxy (TMA) only
#define MBAR_WAIT_RELAXED(addr, ph) do {                                      \
    asm volatile("{\n\t.reg .pred P1;\n\t"                                    \
        "WAIT_%=:\n\t"                                                        \
        "mbarrier.try_wait.parity.relaxed.cta.shared::cta.b64 P1, [%0], %1, 0x989680;\n\t" \
        "@P1 bra.uni DONE_%=;\n\t"                                            \
        "bra.uni WAIT_%=;\n\t"                                                \
        "DONE_%=:\n\t}"                                                       \
        :: "r"(addr), "r"(ph) : "memory");                                    \
} while (0)

#define TMA_LOAD_2D(dst, map, cx, cy, mbar) \
    asm volatile("cp.async.bulk.tensor.2d.shared::cta.global.tile.mbarrier::complete_tx::bytes " \
                 "[%0], [%1, {%2, %3}], [%4];" \
                 :: "r"(dst), "l"(map), "r"(cx), "r"(cy), "r"(mbar) : "memory")

#define FENCE_PROXY_ASYNC() \
    asm volatile("fence.proxy.async.shared::cta;" ::: "memory")

#define LDSM4(r0, r1, r2, r3, addr)                                           \
    asm volatile("ldmatrix.sync.aligned.m8n8.x4.shared.b16 {%0,%1,%2,%3}, [%4];" \
        : "=r"(r0), "=r"(r1), "=r"(r2), "=r"(r3) : "r"(addr))

#define MMA_F16(d, a, b0, b1)                                                 \
    asm volatile("mma.sync.aligned.m16n8k16.row.col.f32.f16.f16.f32 "         \
        "{%0,%1,%2,%3}, {%4,%5,%6,%7}, {%8,%9}, {%0,%1,%2,%3};"               \
        : "+f"((d)[0]), "+f"((d)[1]), "+f"((d)[2]), "+f"((d)[3])              \
        : "r"((a)[0]), "r"((a)[1]), "r"((a)[2]), "r"((a)[3]),                 \
          "r"(b0), "r"(b1))

// -------------------- fused prologue: x->fp16, sign(w)->fp16 ---------------
__global__ void prep_kernel(const float4* __restrict__ x,
                            const float4* __restrict__ w,
                            int n4x, int n4w) {
    int i = blockIdx.x * blockDim.x + threadIdx.x;
    if (i < n4x) {
        float4 v = x[i];
        __half2* dst = reinterpret_cast<__half2*>(g_A) + (size_t)i * 2;
        dst[0] = __floats2half2_rn(v.x, v.y);
        dst[1] = __floats2half2_rn(v.z, v.w);
    } else {
        int j = i - n4x;
        if (j < n4w) {
            float4 v = w[j];
            float sx = (float)((v.x > 0.0f) - (v.x < 0.0f));
            float sy = (float)((v.y > 0.0f) - (v.y < 0.0f));
            float sz = (float)((v.z > 0.0f) - (v.z < 0.0f));
            float sw = (float)((v.w > 0.0f) - (v.w < 0.0f));
            __half2* dst = reinterpret_cast<__half2*>(g_B) + (size_t)j * 2;
            dst[0] = __floats2half2_rn(sx, sy);
            dst[1] = __floats2half2_rn(sz, sw);
        }
    }
}

// ------------------------------- GEMM kernel -------------------------------
// CTA tile 256(M) x 128(N), K-step 64 halves (128 B rows). 4-stage TMA ring
// (48 KB/stage) with FULL (tx-count) + EMPTY (8 warp arrivals) barriers.
// 256 threads = 8 warps (4x2); warp tile 64x64, 128 f32 accs / thread.

static constexpr int STAGES      = 4;
static constexpr int A_STG       = 32768;           // 256 rows x 128 B
static constexpr int B_STG       = 16384;           // 128 rows x 128 B
static constexpr int STAGE_BYTES = A_STG + B_STG;   // 48 KB
static constexpr int KITERS      = K_TOTAL / 64;    // 64
static constexpr int SMEM_DYN    = 1024 + 1024 + STAGES * STAGE_BYTES;

__global__ void __launch_bounds__(256, 1) ternary_gemm_kernel(
    const __grid_constant__ CUtensorMap tma_a,
    const __grid_constant__ CUtensorMap tma_b,
    float* __restrict__ out)
{
    extern __shared__ uint8_t smem_raw[];
    const uint32_t sb    = smem_u32(smem_raw);
    const uint32_t base  = (sb + 1023u) & ~1023u;
    const uint32_t FULLB = base;          // 4 x 8B
    const uint32_t EMPTB = base + 64;     // 4 x 8B
    const uint32_t TILES = base + 1024;

    const int tid  = threadIdx.x;
    const int wid  = tid >> 5;
    const int lane = tid & 31;
    const int wm   = wid >> 1;            // 0..3  (M)
    const int wn   = wid & 1;             // 0..1  (N)

    // ---- tile mapping, GROUP_M=8 for L2 reuse ----
    constexpr int TILES_N = N_TOTAL / 128;   // 128
    constexpr int GROUP_M = 8;               // of 32 M-tiles
    const int per_group = GROUP_M * TILES_N;
    const int grp = blockIdx.x / per_group;
    const int ing = blockIdx.x % per_group;
    const int mt_tile = grp * GROUP_M + (ing % GROUP_M);
    const int nt_tile = ing / GROUP_M;
    const int gm = mt_tile * 256;
    const int gn = nt_tile * 128;

    // ---- init barriers ----
    if (tid == 0) {
        #pragma unroll
        for (int s = 0; s < STAGES; s++) {
            MBAR_INIT(FULLB + 8 * s, 1);
            MBAR_INIT(EMPTB + 8 * s, 8);      // 8 warps arrive
        }
        FENCE_PROXY_ASYNC();
    }
    __syncthreads();   // only CTA-wide barrier in the kernel

    // ---- prologue: fill stages 0..STAGES-2 (first fills, no EMPTY wait) ----
    if (tid == 0) {
        #pragma unroll
        for (int s = 0; s < STAGES - 1; s++) {
            MBAR_EXPECT_TX(FULLB + 8 * s, (uint32_t)STAGE_BYTES);
            const uint32_t tb = TILES + s * STAGE_BYTES;
            TMA_LOAD_2D(tb,         &tma_a, s * 64, gm, FULLB + 8 * s);
            TMA_LOAD_2D(tb + A_STG, &tma_b, s * 64, gn, FULLB + 8 * s);
        }
    }

    // ---- per-lane ldmatrix address pieces (SW128 layout, verified R2-R5) ---
    const int mi  = lane >> 3;
    const int r   = lane & 7;
    const int hi2 = mi >> 1;
    const uint32_t a_row_off = (uint32_t)(wm * 64 + (mi & 1) * 8 + r) * 128;
    const uint32_t b_row_off = (uint32_t)(wn * 64 + hi2 * 8 + r) * 128;

    // ---- accumulators: [mt(4)][nt(8)][4] f32 = 128 regs ----
    float acc[4][8][4];
    #pragma unroll
    for (int a = 0; a < 4; a++)
        #pragma unroll
        for (int b = 0; b < 8; b++)
            #pragma unroll
            for (int c = 0; c < 4; c++) acc[a][b][c] = 0.0f;

    // ---- main loop ----
    for (int kt = 0; kt < KITERS; kt++) {
        const int s = kt & (STAGES - 1);
        const uint32_t full_ph = (uint32_t)((kt >> 2) & 1);
        MBAR_WAIT(FULLB + 8 * s, full_ph);

        const uint32_t sa  = TILES + s * STAGE_BYTES;
        const uint32_t sbb = sa + A_STG;

        #pragma unroll
        for (int kc = 0; kc < 4; kc++) {   // 4 x k16 per 128B chunk
            const uint32_t ax = (uint32_t)((((kc << 1) | hi2) ^ r) << 4);
            const uint32_t bx = (uint32_t)((((kc << 1) | (mi & 1)) ^ r) << 4);

            uint32_t af[4][4], bf[8][2];
            #pragma unroll
            for (int mt = 0; mt < 4; mt++)
                LDSM4(af[mt][0], af[mt][1], af[mt][2], af[mt][3],
                      sa + a_row_off + mt * 2048 + ax);
            #pragma unroll
            for (int j = 0; j < 4; j++)
                LDSM4(bf[2 * j][0], bf[2 * j][1], bf[2 * j + 1][0], bf[2 * j + 1][1],
                      sbb + b_row_off + j * 2048 + bx);

            #pragma unroll
            for (int mt = 0; mt < 4; mt++)
                #pragma unroll
                for (int nt = 0; nt < 8; nt++)
                    MMA_F16(acc[mt][nt], af[mt], bf[nt][0], bf[nt][1]);
        }

        // this warp is done with stage s (all MMAs consuming it have issued)
        if (lane == 0) MBAR_ARRIVE(EMPTB + 8 * s);

        // refill stage for iteration kt+STAGES-1 (after compute: 2-stage slack)
        if (tid == 0 && kt + STAGES - 1 < KITERS) {
            const int f  = kt + STAGES - 1;
            const int ns = f & (STAGES - 1);
            const int n  = f >> 2;                     // fill instance
            if (n >= 1) {                              // wait prior consumption
                MBAR_WAIT_RELAXED(EMPTB + 8 * ns, (uint32_t)((n - 1) & 1));
            }
            MBAR_EXPECT_TX(FULLB + 8 * ns, (uint32_t)STAGE_BYTES);
            const uint32_t tb = TILES + ns * STAGE_BYTES;
            const int kx = f * 64;
            TMA_LOAD_2D(tb,         &tma_a, kx, gm, FULLB + 8 * ns);
            TMA_LOAD_2D(tb + A_STG, &tma_b, kx, gn, FULLB + 8 * ns);
        }
    }

    // ---- epilogue (per-warp independent) ----
    const int rbase = gm + wm * 64 + (lane >> 2);
    const int cbase = gn + wn * 64 + (lane & 3) * 2;
    #pragma unroll
    for (int mt = 0; mt < 4; mt++) {
        const int r0 = rbase + mt * 16;
        #pragma unroll
        for (int nt = 0; nt < 8; nt++) {
            const int c = cbase + nt * 8;
            float2 v;
            v.x = acc[mt][nt][0];
            v.y = acc[mt][nt][1];
            *reinterpret_cast<float2*>(out + (size_t)r0 * N_TOTAL + c) = v;
            v.x = acc[mt][nt][2];
            v.y = acc[mt][nt][3];
            *reinterpret_cast<float2*>(out + (size_t)(r0 + 8) * N_TOTAL + c) = v;
        }
    }
}

// ------------------------------- host side ---------------------------------
typedef CUresult (*encode_fn_t)(CUtensorMap*, CUtensorMapDataType, cuuint32_t,
                                void*, const cuuint64_t*, const cuuint64_t*,
                                const cuuint32_t*, const cuuint32_t*,
                                CUtensorMapInterleave, CUtensorMapSwizzle,
                                CUtensorMapL2promotion, CUtensorMapFloatOOBfill);

static void make_map_f16(CUtensorMap* m, void* ptr,
                         uint64_t inner, uint64_t outer,
                         uint32_t box_i, uint32_t box_o) {
    encode_fn_t fn = nullptr;
    cudaDriverEntryPointQueryResult st;
    cudaGetDriverEntryPointByVersion("cuTensorMapEncodeTiled", (void**)&fn,
                                     12000, cudaEnableDefault, &st);
    if (!fn) return;
    cuuint64_t dims[2]    = {inner, outer};
    cuuint64_t strides[1] = {inner * 2};      // bytes (fp16)
    cuuint32_t box[2]     = {box_i, box_o};
    cuuint32_t es[2]      = {1, 1};
    fn(m, CU_TENSOR_MAP_DATA_TYPE_UINT16, 2, ptr, dims, strides, box, es,
       CU_TENSOR_MAP_INTERLEAVE_NONE, CU_TENSOR_MAP_SWIZZLE_128B,
       CU_TENSOR_MAP_L2_PROMOTION_L2_128B, CU_TENSOR_MAP_FLOAT_OOB_FILL_NONE);
}

extern "C" void kernel_launch(void* const* d_in, const int* in_sizes, int n_in,
                              void* d_out, int out_size) {
    const float* x = (const float*)d_in[0];   // [2,4096,4096]
    const float* w = (const float*)d_in[1];   // [16384,4096]
    float* out = (float*)d_out;               // [2,4096,16384]

    // fused prologue (1 launch so ncu -s5 -c1 lands on the GEMM)
    {
        const int n4x = (M_TOTAL * K_TOTAL) / 4;
        const int n4w = (N_TOTAL * K_TOTAL) / 4;
        const int total = n4x + n4w;
        prep_kernel<<<(total + 255) / 256, 256>>>((const float4*)x,
                                                  (const float4*)w, n4x, n4w);
    }

    void *p_a = nullptr, *p_b = nullptr;
    cudaGetSymbolAddress(&p_a, g_A);
    cudaGetSymbolAddress(&p_b, g_B);

    CUtensorMap mA, mB;
    make_map_f16(&mA, p_a, K_TOTAL, M_TOTAL, 64, 256);
    make_map_f16(&mB, p_b, K_TOTAL, N_TOTAL, 64, 128);

    cudaFuncSetAttribute(ternary_gemm_kernel,
                         cudaFuncAttributeMaxDynamicSharedMemorySize, SMEM_DYN);

    const int grid = (M_TOTAL / 256) * (N_TOTAL / 128);   // 32 * 128 = 4096
    ternary_gemm_kernel<<<grid, 256, SMEM_DYN>>>(mA, mB, out);
}